// round 16
// baseline (speedup 1.0000x reference)
#include <cuda_runtime.h>
#include <cstdint>
#include <math.h>

#define N_ROWS 8192
#define D_COLS 1024
#define S_COLS 8
#define NC 80
#define NU 88
#define NUP 96
#define NPAIR 640
#define KPARTS 32
#define EPSF 1e-10f

// ---------------- scratch (no allocations allowed) ----------------
__device__ float  g_B[S_COLS * D_COLS];   // S^T A  (8 x 1024)
__device__ double g_a2d[D_COLS];          // ||A_j||^2 (double)
__device__ double g_S2d[S_COLS];          // ||S_c||^2 (double)
__device__ int    g_match[D_COLS];
__device__ int    g_sel[S_COLS];
__device__ int    g_Cidx[NC];
__device__ int    g_U[NUP];
__device__ double g_Afro2d;
__device__ int    g_offset;
__device__ float  g_Asub[N_ROWS * NUP];   // A[:, U]   (8192 x 96)
__device__ float  g_Cpart[KPARTS * D_COLS * NUP];  // k-split partials of C
__device__ float  g_Csub[D_COLS * NUP];   // K[:, U]   (1024 x 96), deterministic
__device__ float  g_Ksub[NU * NU];
__device__ float  g_K2sub[NU * NU];
__device__ float  g_K2part[4 * NU * NU];
__device__ int    g_needfix[NPAIR];
__device__ double g_obj[NPAIR];
__device__ int    g_out[S_COLS];

// ---------------- packed f32x2 helpers (Blackwell) ----------------
__device__ __forceinline__ unsigned long long pk2(float x, float y) {
    unsigned long long r;
    asm("mov.b64 %0, {%1, %2};" : "=l"(r) : "f"(x), "f"(y));
    return r;
}
__device__ __forceinline__ void upk2(unsigned long long v, float& x, float& y) {
    asm("mov.b64 {%0, %1}, %2;" : "=f"(x), "=f"(y) : "l"(v));
}
__device__ __forceinline__ void fma2(unsigned long long& d,
                                     unsigned long long a, unsigned long long b) {
    asm("fma.rn.f32x2 %0, %1, %2, %3;" : "=l"(d) : "l"(a), "l"(b), "l"(d));
}

// ---------------- cp.async helpers ----------------
__device__ __forceinline__ unsigned smem_u32(const void* p) {
    return (unsigned)__cvta_generic_to_shared(p);
}
#define CP_ASYNC16(dst_u32, src_ptr) \
    asm volatile("cp.async.cg.shared.global [%0], [%1], 16;" \
                 :: "r"(dst_u32), "l"(src_ptr))
#define CP_COMMIT() asm volatile("cp.async.commit_group;" ::: "memory")
#define CP_WAIT1()  asm volatile("cp.async.wait_group 1;" ::: "memory")
#define CP_WAIT0()  asm volatile("cp.async.wait_group 0;" ::: "memory")

// ---------------- JAX threefry2x32 (exact) ----------------
__device__ __forceinline__ unsigned tf_rotl(unsigned v, int r) {
    return (v << r) | (v >> (32 - r));
}
__device__ void threefry2x32(unsigned k0, unsigned k1, unsigned x0, unsigned x1,
                             unsigned& o0, unsigned& o1) {
    unsigned ks2 = k0 ^ k1 ^ 0x1BD11BDAu;
    x0 += k0; x1 += k1;
    const int R0[4] = {13, 15, 26, 6};
    const int R1[4] = {17, 29, 16, 24};
#pragma unroll
    for (int i = 0; i < 4; i++) { x0 += x1; x1 = tf_rotl(x1, R0[i]); x1 ^= x0; }
    x0 += k1; x1 += ks2 + 1u;
#pragma unroll
    for (int i = 0; i < 4; i++) { x0 += x1; x1 = tf_rotl(x1, R1[i]); x1 ^= x0; }
    x0 += ks2; x1 += k0 + 2u;
#pragma unroll
    for (int i = 0; i < 4; i++) { x0 += x1; x1 = tf_rotl(x1, R0[i]); x1 ^= x0; }
    x0 += k0; x1 += k1 + 3u;
#pragma unroll
    for (int i = 0; i < 4; i++) { x0 += x1; x1 = tf_rotl(x1, R1[i]); x1 ^= x0; }
    x0 += k1; x1 += ks2 + 4u;
#pragma unroll
    for (int i = 0; i < 4; i++) { x0 += x1; x1 = tf_rotl(x1, R0[i]); x1 ^= x0; }
    x0 += ks2; x1 += k0 + 5u;
    o0 = x0; o1 = x1;
}
__device__ __forceinline__ unsigned tf_bits(unsigned k0, unsigned k1,
                                            unsigned x0, unsigned x1) {
    unsigned o0, o1; threefry2x32(k0, k1, x0, x1, o0, o1);
    return o0 ^ o1;
}

// ---------------- symmetric Jacobi eigensolver (double, n<=9) ----------------
__device__ void jacobi_sym(double* A, double* V, int n) {
    for (int i = 0; i < n * n; i++) V[i] = 0.0;
    for (int i = 0; i < n; i++) V[i * n + i] = 1.0;
    for (int sweep = 0; sweep < 20; sweep++) {
        double off = 0.0, dsc = 1e-300;
        for (int p = 0; p < n; p++) {
            dsc += A[p * n + p] * A[p * n + p];
            for (int q = p + 1; q < n; q++) off += A[p * n + q] * A[p * n + q];
        }
        if (off <= dsc * 1e-28) break;
        for (int p = 0; p < n - 1; p++)
            for (int q = p + 1; q < n; q++) {
                double apq = A[p * n + q];
                if (fabs(apq) < 1e-300) continue;
                double app = A[p * n + p], aqq = A[q * n + q];
                double theta = 0.5 * (aqq - app) / apq;
                double t = ((theta >= 0.0) ? 1.0 : -1.0) /
                           (fabs(theta) + sqrt(1.0 + theta * theta));
                double c = 1.0 / sqrt(1.0 + t * t), s = t * c;
                for (int k2 = 0; k2 < n; k2++) {
                    if (k2 == p || k2 == q) continue;
                    double akp = A[k2 * n + p], akq = A[k2 * n + q];
                    A[k2 * n + p] = A[p * n + k2] = c * akp - s * akq;
                    A[k2 * n + q] = A[q * n + k2] = s * akp + c * akq;
                }
                A[p * n + p] = app - t * apq;
                A[q * n + q] = aqq + t * apq;
                A[p * n + q] = A[q * n + p] = 0.0;
                for (int k2 = 0; k2 < n; k2++) {
                    double vkp = V[k2 * n + p], vkq = V[k2 * n + q];
                    V[k2 * n + p] = c * vkp - s * vkq;
                    V[k2 * n + q] = s * vkp + c * vkq;
                }
            }
    }
}

// ---------------- kernels ----------------

// per-column ||A_j||^2 (Kahan fp32 -> double) and B = S^T A (f32x2 packed).
// float4 loads: thread owns 4 consecutive columns; per-column row order
// unchanged -> bit-identical g_a2d / g_B partials.
__global__ void stats_kernel(const float* __restrict__ A, const float* __restrict__ S) {
    int tid = threadIdx.x;                 // 256
    int r0 = blockIdx.x * 32;              // 256 blocks
    float a2s[4], a2c[4];
    unsigned long long bacc2[4][4];
    double s2acc = 0.0;
#pragma unroll
    for (int a = 0; a < 4; a++) {
        a2s[a] = 0.0f; a2c[a] = 0.0f;
#pragma unroll
        for (int b = 0; b < 4; b++) bacc2[a][b] = 0ULL;
    }
    for (int rr = 0; rr < 32; rr++) {
        int row = r0 + rr;
        float sv[8];
#pragma unroll
        for (int c = 0; c < 8; c++) sv[c] = __ldg(&S[row * 8 + c]);
        unsigned long long svp[4];
#pragma unroll
        for (int c = 0; c < 4; c++) svp[c] = pk2(sv[2 * c], sv[2 * c + 1]);
        if (tid < 8) s2acc += (double)sv[tid] * (double)sv[tid];
        float4 v4 = *(const float4*)&A[(size_t)row * D_COLS + tid * 4];
        float vv4[4] = {v4.x, v4.y, v4.z, v4.w};
#pragma unroll
        for (int comp = 0; comp < 4; comp++) {
            float v = vv4[comp];
            float y = fmaf(v, v, -a2c[comp]);
            float t = a2s[comp] + y;
            a2c[comp] = (t - a2s[comp]) - y;
            a2s[comp] = t;
            unsigned long long vv = pk2(v, v);
#pragma unroll
            for (int c = 0; c < 4; c++) fma2(bacc2[comp][c], vv, svp[c]);
        }
    }
#pragma unroll
    for (int comp = 0; comp < 4; comp++) {
        int col = tid * 4 + comp;
        atomicAdd(&g_a2d[col], (double)a2s[comp] + (double)a2c[comp]);
#pragma unroll
        for (int c = 0; c < 4; c++) {
            float lo, hi;
            upk2(bacc2[comp][c], lo, hi);
            atomicAdd(&g_B[(2 * c) * D_COLS + col], lo);
            atomicAdd(&g_B[(2 * c + 1) * D_COLS + col], hi);
        }
    }
    if (tid < 8) atomicAdd(&g_S2d[tid], s2acc);
}

// merged: G_S, inv(G_S), col_norms, match, logits, sel, offset, bitonic top-80
__global__ void __launch_bounds__(1024) setup_topk_kernel(const float* __restrict__ S) {
    __shared__ float sTri[36];
    __shared__ float sGS[64];
    __shared__ double sred[1024];
    __shared__ double sW[64];
    __shared__ float sWf[64];
    __shared__ double sSn[8];
    __shared__ double sL[64];
    __shared__ int sFallback;
    __shared__ float sv_[D_COLS];
    __shared__ int six_[D_COLS];
    int tid = threadIdx.x;       // 1024
    int lane = tid & 31;
    if (tid < 36) sTri[tid] = 0.0f;
    if (tid == 0) sFallback = 0;
    __syncthreads();

    // G_S = S^T S
    {
        float g[36];
#pragma unroll
        for (int i = 0; i < 36; i++) g[i] = 0.0f;
        for (int r = tid; r < N_ROWS; r += 1024) {
            float sv[8];
#pragma unroll
            for (int c = 0; c < 8; c++) sv[c] = S[r * 8 + c];
            int w = 0;
#pragma unroll
            for (int c = 0; c < 8; c++)
#pragma unroll
                for (int d = c; d < 8; d++) { g[w] += sv[c] * sv[d]; w++; }
        }
#pragma unroll
        for (int i = 0; i < 36; i++) {
            float x = g[i];
#pragma unroll
            for (int off = 16; off; off >>= 1)
                x += __shfl_down_sync(0xffffffffu, x, off);
            if (lane == 0) atomicAdd(&sTri[i], x);
        }
    }
    __syncthreads();
    if (tid < 64) {
        int c = tid >> 3, d = tid & 7;
        int lo = c < d ? c : d, hi = c < d ? d : c;
        int w = lo * 8 - lo * (lo - 1) / 2 + (hi - lo);
        sGS[tid] = sTri[w];
    }
    if (tid >= 64 && tid < 72) sSn[tid - 64] = sqrt(g_S2d[tid - 64]);

    // A_fro2
    {
        double p = (tid < D_COLS) ? g_a2d[tid] : 0.0;
        sred[tid] = p; __syncthreads();
        for (int st = 512; st > 0; st >>= 1) {
            if (tid < st) sred[tid] += sred[tid + st];
            __syncthreads();
        }
        if (tid == 0) g_Afro2d = sred[0];
        __syncthreads();
    }

    // inv(G_S) via Cholesky; fallback Jacobi pinv
    if (tid == 0) {
        double L[64];
        int ok = 1;
        for (int c = 0; c < 8 && ok; c++) {
            double d = (double)sGS[c * 8 + c];
            for (int k = 0; k < c; k++) d -= L[c * 8 + k] * L[c * 8 + k];
            if (d <= 0.0) { ok = 0; break; }
            double lc = sqrt(d);
            L[c * 8 + c] = lc;
            for (int r = c + 1; r < 8; r++) {
                double v = (double)sGS[r * 8 + c];
                for (int k = 0; k < c; k++) v -= L[r * 8 + k] * L[c * 8 + k];
                L[r * 8 + c] = v / lc;
            }
        }
        if (ok) {
            for (int i = 0; i < 64; i++) sL[i] = L[i];
        } else {
            sFallback = 1;
            double Ad[64], Vd[64];
            for (int i = 0; i < 64; i++) Ad[i] = (double)sGS[i];
            jacobi_sym(Ad, Vd, 8);
            double lmax = 0.0;
            for (int r = 0; r < 8; r++) lmax = fmax(lmax, fabs(Ad[r * 8 + r]));
            double cut = 9.5367431640625e-06 * lmax;
            for (int c = 0; c < 8; c++)
                for (int d = 0; d < 8; d++) {
                    double w = 0.0;
                    for (int r = 0; r < 8; r++) {
                        double lam = Ad[r * 8 + r];
                        if (fabs(lam) > cut) w += Vd[c * 8 + r] * Vd[d * 8 + r] / lam;
                    }
                    sW[c * 8 + d] = w;
                }
        }
    }
    __syncthreads();
    if (!sFallback && tid < 8) {
        double y[8], x[8];
        for (int r = 0; r < 8; r++) {
            double v = (r == tid) ? 1.0 : 0.0;
            for (int k = 0; k < r; k++) v -= sL[r * 8 + k] * y[k];
            y[r] = v / sL[r * 8 + r];
        }
        for (int r = 7; r >= 0; r--) {
            double v = y[r];
            for (int k = r + 1; k < 8; k++) v -= sL[k * 8 + r] * x[k];
            x[r] = v / sL[r * 8 + r];
        }
        for (int r = 0; r < 8; r++) sW[r * 8 + tid] = x[r];
    }
    __syncthreads();
    if (tid < 64) sWf[tid] = (float)sW[tid];
    __syncthreads();

    // col_norms in fp32 (feeds only Gumbel logits); match on double norms
    float cn;
    {
        int j = tid;
        float b[8];
#pragma unroll
        for (int c = 0; c < 8; c++) b[c] = g_B[c * D_COLS + j];
        float q = 0.0f;
#pragma unroll
        for (int c = 0; c < 8; c++) {
            float w = 0.0f;
#pragma unroll
            for (int d = 0; d < 8; d++) w += sWf[c * 8 + d] * b[d];
            q += b[c] * w;
        }
        double a2 = g_a2d[j];
        cn = fmaxf((float)a2 - q, 0.0f);
        double an = sqrt(a2);
        double th = 1e-5 * (an + 1e-10);
        int mt = 0;
#pragma unroll
        for (int c = 0; c < 8; c++)
            if (fabs(sSn[c] - an) < th) mt = 1;
        g_match[j] = mt;
    }
    __syncthreads();

    // denominator (double tree; common shift -> ordering-invariant)
    sred[tid] = (double)cn;
    __syncthreads();
    for (int st = 512; st > 0; st >>= 1) {
        if (tid < st) sred[tid] += sred[tid + st];
        __syncthreads();
    }
    float denom = (float)sred[0];
    __syncthreads();

    // logits
    {
        unsigned kg0, kg1;
        threefry2x32(0u, 42u, 0u, 0u, kg0, kg1);
        unsigned bits = tf_bits(kg0, kg1, 0u, (unsigned)tid);
        float u = __uint_as_float((bits >> 9) | 0x3f800000u) - 1.0f;
        u = fmaxf(u, 0.0f);
        float gum = -logf(-logf(u + EPSF) + EPSF);
        sv_[tid] = logf(cn / (denom + EPSF) + EPSF) + gum;
        six_[tid] = tid;
    }

    if (tid == 0) {
        unsigned km0, km1;
        threefry2x32(0u, 42u, 0u, 1u, km0, km1);
        unsigned k1a, k1b, k2a, k2b;
        threefry2x32(km0, km1, 0u, 0u, k1a, k1b);
        threefry2x32(km0, km1, 0u, 1u, k2a, k2b);
        unsigned hb = tf_bits(k1a, k1b, 0u, 0u);
        unsigned lb = tf_bits(k2a, k2b, 0u, 0u);
        g_offset = (int)((((hb % 80u) * 16u) + (lb % 80u)) % 80u);
    }
    __syncthreads();
    if (tid == 0) {
        int cnt = 0;
        int selL[8];
        for (int j = 0; j < D_COLS && cnt < 8; j++)
            if (g_match[j]) selL[cnt++] = j;
        for (int j = 0; j < D_COLS && cnt < 8; j++)
            if (!g_match[j]) selL[cnt++] = j;
        for (int x = 1; x < 8; x++) {
            int v = selL[x], y = x - 1;
            while (y >= 0 && selL[y] > v) { selL[y + 1] = selL[y]; y--; }
            selL[y + 1] = v;
        }
        for (int c = 0; c < 8; c++) { g_sel[c] = selL[c]; g_U[c] = selL[c]; }
    }
    __syncthreads();

    // bitonic sort (value desc, ties -> lower index)
    for (int k = 2; k <= D_COLS; k <<= 1) {
        for (int j = k >> 1; j > 0; j >>= 1) {
            int l = tid ^ j;
            if (l > tid) {
                float vi = sv_[tid], vl = sv_[l];
                int ii = six_[tid], il = six_[l];
                bool lt = (vl > vi) || (vl == vi && il < ii);
                bool dirAsc = ((tid & k) == 0);
                if (lt == dirAsc) {
                    sv_[tid] = vl; sv_[l] = vi;
                    six_[tid] = il; six_[l] = ii;
                }
            }
            __syncthreads();
        }
    }
    if (tid < NC) { g_Cidx[tid] = six_[tid]; g_U[8 + tid] = six_[tid]; }
    if (tid >= NU && tid < NUP) g_U[tid] = g_sel[0];   // padding
}

__global__ void gather_kernel(const float* __restrict__ A) {
    int t = blockIdx.x * blockDim.x + threadIdx.x;
    if (t >= N_ROWS * NUP) return;
    int i = t / NUP, u = t - i * NUP;
    g_Asub[t] = A[(size_t)i * D_COLS + g_U[u]];
}

// C = A^T * Asub (1024 x 96): round-14 proven config — cp.async double-buffer,
// 256 threads, 4j x 12u tiling, 2 blocks/SM, deterministic k-partial STG.
__global__ void __launch_bounds__(256, 2) matmul_C_kernel(const float* __restrict__ A) {
    __shared__ __align__(16) float sA[2][16][128];
    __shared__ __align__(16) float sB[2][16][NUP];
    int j0 = blockIdx.x * 128;       // 8 j-tiles
    int part = blockIdx.y;           // 32 k-parts
    int i0 = part * 256;
    int tid = threadIdx.x;           // 256
    int tj = (tid & 31) * 4;         // 4 consecutive j
    int tu = (tid >> 5) * 12;        // 12 consecutive u
    unsigned long long acc2[4][6];
#pragma unroll
    for (int a = 0; a < 4; a++)
#pragma unroll
        for (int p = 0; p < 6; p++) acc2[a][p] = 0ULL;

    // copy slots: sA = 512 float4 (2/thread), sB = 384 float4 (1.5/thread)
    int aR0 = tid >> 5;                     // 0..7
    int aR1 = (tid + 256) >> 5;             // 8..15
    int aC  = (tid & 31) * 4;
    int bR0 = tid / 24,         bC0 = (tid % 24) * 4;
    int bR1 = (tid + 256) / 24, bC1 = ((tid + 256) % 24) * 4;
    bool hasB1 = tid < 128;

#define MM_ISSUE(ch, buf) do {                                               \
        int ib_ = i0 + (ch) * 16;                                            \
        CP_ASYNC16(smem_u32(&sA[buf][aR0][aC]),                              \
                   &A[(size_t)(ib_ + aR0) * D_COLS + j0 + aC]);              \
        CP_ASYNC16(smem_u32(&sA[buf][aR1][aC]),                              \
                   &A[(size_t)(ib_ + aR1) * D_COLS + j0 + aC]);              \
        CP_ASYNC16(smem_u32(&sB[buf][bR0][bC0]),                             \
                   &g_Asub[(ib_ + bR0) * NUP + bC0]);                        \
        if (hasB1)                                                           \
            CP_ASYNC16(smem_u32(&sB[buf][bR1][bC1]),                         \
                       &g_Asub[(ib_ + bR1) * NUP + bC1]);                    \
        CP_COMMIT();                                                         \
    } while (0)

    MM_ISSUE(0, 0);
    for (int ch = 0; ch < 16; ch++) {
        int buf = ch & 1;
        if (ch < 15) { MM_ISSUE(ch + 1, buf ^ 1); CP_WAIT1(); }
        else         { CP_WAIT0(); }
        __syncthreads();
#pragma unroll
        for (int kk = 0; kk < 16; kk++) {
            float4 aj = *(float4*)&sA[buf][kk][tj];
            unsigned long long avp[4];
            avp[0] = pk2(aj.x, aj.x);
            avp[1] = pk2(aj.y, aj.y);
            avp[2] = pk2(aj.z, aj.z);
            avp[3] = pk2(aj.w, aj.w);
            ulonglong2 q0 = *(const ulonglong2*)&sB[buf][kk][tu];
            ulonglong2 q1 = *(const ulonglong2*)&sB[buf][kk][tu + 4];
            ulonglong2 q2 = *(const ulonglong2*)&sB[buf][kk][tu + 8];
            unsigned long long bv[6] = {q0.x, q0.y, q1.x, q1.y, q2.x, q2.y};
#pragma unroll
            for (int p = 0; p < 6; p++)
#pragma unroll
                for (int a = 0; a < 4; a++) fma2(acc2[a][p], avp[a], bv[p]);
        }
        __syncthreads();
    }
#undef MM_ISSUE
    float* dst = &g_Cpart[(size_t)part * (D_COLS * NUP)];
#pragma unroll
    for (int a = 0; a < 4; a++) {
        int base = (j0 + tj + a) * NUP + tu;
#pragma unroll
        for (int p = 0; p < 6; p++) {
            float lo, hi;
            upk2(acc2[a][p], lo, hi);
            __stwt((float2*)&dst[base + 2 * p], make_float2(lo, hi));
        }
    }
}

// deterministic sum of k-partials -> Csub (fixed ascending part order)
__global__ void csub_sum_kernel() {
    int t = blockIdx.x * blockDim.x + threadIdx.x;
    if (t >= D_COLS * NUP) return;
    float s = 0.0f;
#pragma unroll 4
    for (int p = 0; p < KPARTS; p++)
        s += g_Cpart[(size_t)p * (D_COLS * NUP) + t];
    g_Csub[t] = s;
}

// K2 partials = C^T C over m-quarter (deterministic, no atomics)
__global__ void ksub_part_kernel() {
    __shared__ float sI[32][17];
    __shared__ float sJ[32][17];
    int i0 = blockIdx.y * 16, j0 = blockIdx.x * 16;
    int mz = blockIdx.z;                      // 0..3
    int tx = threadIdx.x, ty = threadIdx.y;   // 16 x 16
    float acc = 0.0f;
    for (int m0 = mz * 256; m0 < mz * 256 + 256; m0 += 32) {
        int r = ty * 2 + (tx >> 3);
        int c = tx & 7;
        sI[r][c * 2]     = g_Csub[(m0 + r) * NUP + i0 + c * 2];
        sI[r][c * 2 + 1] = g_Csub[(m0 + r) * NUP + i0 + c * 2 + 1];
        sJ[r][c * 2]     = g_Csub[(m0 + r) * NUP + j0 + c * 2];
        sJ[r][c * 2 + 1] = g_Csub[(m0 + r) * NUP + j0 + c * 2 + 1];
        __syncthreads();
#pragma unroll
        for (int mm = 0; mm < 32; mm++)
            acc += sI[mm][ty] * sJ[mm][tx];
        __syncthreads();
    }
    int i = i0 + ty, j = j0 + tx;
    if (i < NU && j < NU)
        g_K2part[mz * NU * NU + i * NU + j] = acc;
}

__global__ void ksub_sum_kernel() {
    int t = blockIdx.x * blockDim.x + threadIdx.x;
    if (t >= NU * NU) return;
    int i = t / NU, j = t - i * NU;
    g_K2sub[t] = ((g_K2part[t] + g_K2part[NU * NU + t]) +
                  g_K2part[2 * NU * NU + t]) + g_K2part[3 * NU * NU + t];
    g_Ksub[t] = g_Csub[g_U[i] * NUP + j];
}

// fully-unrolled Cholesky + trace(G^-1 M), operands read from global (hot L2)
template <int N>
__device__ bool chol_trace(const int* idx, double& out) {
    double L[N * N];
#pragma unroll
    for (int c = 0; c < N; c++) {
        double d = (double)g_Ksub[idx[c] * NU + idx[c]];
#pragma unroll
        for (int k = 0; k < N; k++)
            if (k < c) d -= L[c * N + k] * L[c * N + k];
        if (d <= 0.0) return false;
        double lc = sqrt(d);
        L[c * N + c] = lc;
#pragma unroll
        for (int r = 0; r < N; r++)
            if (r > c) {
                double v = (double)g_Ksub[idx[r] * NU + idx[c]];
#pragma unroll
                for (int k = 0; k < N; k++)
                    if (k < c) v -= L[r * N + k] * L[c * N + k];
                L[r * N + c] = v / lc;
            }
    }
    double sum = 0.0;
#pragma unroll
    for (int c = 0; c < N; c++) {
        double y[N], x[N];
#pragma unroll
        for (int r = 0; r < N; r++) {
            double v = (double)g_K2sub[idx[r] * NU + idx[c]];
#pragma unroll
            for (int k = 0; k < N; k++)
                if (k < r) v -= L[r * N + k] * y[k];
            y[r] = v / L[r * N + r];
        }
#pragma unroll
        for (int r = N - 1; r >= 0; r--) {
            double v = y[r];
#pragma unroll
            for (int k = 0; k < N; k++)
                if (k > r) v -= L[k * N + r] * x[k];
            x[r] = v / L[r * N + r];
        }
        sum += x[c];
    }
    out = sum;
    return true;
}

// fast path only; flags hard cases for finalize's fixup
__global__ void pairs_fast_kernel() {
    int pid = blockIdx.x * blockDim.x + threadIdx.x;
    if (pid >= NPAIR) return;
    int a = pid >> 3, qpos = pid & 7;
    int pg = g_Cidx[a];
    bool pMasked = (pg == g_sel[qpos]);
    bool dup = false;
#pragma unroll
    for (int r = 0; r < 8; r++)
        if (r != qpos && g_sel[r] == pg) dup = true;
    if (dup) { g_needfix[pid] = 1; return; }
    int idx[9]; int n = 0;
#pragma unroll
    for (int r = 0; r < 8; r++)
        if (r != qpos) idx[n++] = r;
    if (!pMasked) idx[n++] = 8 + a;
    double sum;
    bool ok = pMasked ? chol_trace<7>(idx, sum) : chol_trace<8>(idx, sum);
    if (!ok) { g_needfix[pid] = 1; return; }
    g_obj[pid] = sqrt(fmax(g_Afro2d - sum, 0.0));
}

// fixup (rare) + argmin + output-index construction
__global__ void finalize_kernel() {
    int tid = threadIdx.x;   // 256
    for (int pid = tid; pid < NPAIR; pid += 256) {
        if (!g_needfix[pid]) continue;
        int a = pid >> 3, qpos = pid & 7;
        int pg = g_Cidx[a];
        double m[9];
#pragma unroll
        for (int r = 0; r < 9; r++) m[r] = 1.0;
        m[qpos] = 0.0;
        if (pg == g_sel[qpos]) m[8] = 0.0;
        int pos[9];
#pragma unroll
        for (int r = 0; r < 8; r++) pos[r] = r;
        pos[8] = 8 + a;
        double G[81], M[81], V[81];
        for (int r = 0; r < 9; r++)
            for (int c = 0; c < 9; c++) {
                double mm = m[r] * m[c];
                G[r * 9 + c] = mm * (double)g_Ksub[pos[r] * NU + pos[c]];
                M[r * 9 + c] = mm * (double)g_K2sub[pos[r] * NU + pos[c]];
            }
        jacobi_sym(G, V, 9);
        double lmax = 0.0;
        for (int r = 0; r < 9; r++) lmax = fmax(lmax, fabs(G[r * 9 + r]));
        double cutoff = 1.0728836059570312e-05 * lmax;  // 10*9*eps_f32
        double sum = 0.0;
        for (int r = 0; r < 9; r++) {
            double lam = G[r * 9 + r];
            if (fabs(lam) > cutoff) {
                double quad = 0.0;
                for (int i = 0; i < 9; i++) {
                    double wi = 0.0;
                    for (int j = 0; j < 9; j++) wi += M[i * 9 + j] * V[j * 9 + r];
                    quad += V[i * 9 + r] * wi;
                }
                sum += quad / lam;
            }
        }
        g_obj[pid] = sqrt(fmax(g_Afro2d - sum, 0.0));
    }
    __syncthreads();
    if (tid >= 32) return;
    int lane = tid;
    double bv = 1e300; int bi = NPAIR;
    for (int p = lane; p < NPAIR; p += 32) {
        double v = g_obj[p];
        if (v < bv) { bv = v; bi = p; }
    }
#pragma unroll
    for (int off = 16; off; off >>= 1) {
        double ov = __shfl_down_sync(0xffffffffu, bv, off);
        int oi = __shfl_down_sync(0xffffffffu, bi, off);
        if (ov < bv || (ov == bv && oi < bi)) { bv = ov; bi = oi; }
    }
    if (lane != 0) return;
    int qpos = bi & 7;
    int minidx = g_sel[qpos];
    int bestp = g_Cidx[g_offset];
    int out[8]; int cnt = 0;
    for (int j = 0; j < D_COLS && cnt < 8; j++) {
        int f = g_match[j];
        if (j == minidx) f = 0;
        if (j == bestp) f = 1;
        if (f) out[cnt++] = j;
    }
    for (int j = 0; j < D_COLS && cnt < 8; j++) {
        int f = g_match[j];
        if (j == minidx) f = 0;
        if (j == bestp) f = 1;
        if (!f) out[cnt++] = j;
    }
    for (int x = 1; x < 8; x++) {
        int v = out[x], y = x - 1;
        while (y >= 0 && out[y] > v) { out[y + 1] = out[y]; y--; }
        out[y + 1] = v;
    }
    for (int c = 0; c < 8; c++) g_out[c] = out[c];
}

// output gather + re-zero scratch for the next graph replay
__global__ void output_kernel(const float* __restrict__ A, float* __restrict__ out) {
    int t = blockIdx.x * blockDim.x + threadIdx.x;   // 65536 threads
    if (t < N_ROWS * S_COLS) {
        int i = t >> 3, c = t & 7;
        out[t] = A[(size_t)i * D_COLS + g_out[c]];
    }
    if (t < S_COLS * D_COLS) g_B[t] = 0.0f;
    if (t < D_COLS) g_a2d[t] = 0.0;
    if (t < S_COLS) g_S2d[t] = 0.0;
    if (t < NPAIR) g_needfix[t] = 0;
}

// ---------------- launch ----------------
extern "C" void kernel_launch(void* const* d_in, const int* in_sizes, int n_in,
                              void* d_out, int out_size) {
    const float* A = nullptr;
    const float* S = nullptr;
    for (int i = 0; i < n_in; i++) {
        if (in_sizes[i] == N_ROWS * D_COLS) A = (const float*)d_in[i];
        else if (in_sizes[i] == N_ROWS * S_COLS) S = (const float*)d_in[i];
    }
    if (!A) A = (const float*)d_in[0];
    if (!S) S = (const float*)d_in[2];
    float* out = (float*)d_out;

    stats_kernel<<<256, 256>>>(A, S);
    setup_topk_kernel<<<1, 1024>>>(S);
    gather_kernel<<<(N_ROWS * NUP) / 256, 256>>>(A);
    matmul_C_kernel<<<dim3(8, KPARTS), 256>>>(A);
    csub_sum_kernel<<<(D_COLS * NUP + 255) / 256, 256>>>();
    ksub_part_kernel<<<dim3(6, 6, 4), dim3(16, 16)>>>();
    ksub_sum_kernel<<<(NU * NU + 255) / 256, 256>>>();
    pairs_fast_kernel<<<(NPAIR + 63) / 64, 64>>>();
    finalize_kernel<<<1, 256>>>();
    output_kernel<<<(N_ROWS * S_COLS) / 256, 256>>>(A, out);
}

// round 17
// speedup vs baseline: 1.0617x; 1.0617x over previous
#include <cuda_runtime.h>
#include <cstdint>
#include <math.h>

#define N_ROWS 8192
#define D_COLS 1024
#define S_COLS 8
#define NC 80
#define NU 88
#define NUP 96
#define NPAIR 640
#define KPARTS 32
#define EPSF 1e-10f

// ---------------- scratch (no allocations allowed) ----------------
__device__ float  g_B[S_COLS * D_COLS];   // S^T A  (8 x 1024)
__device__ double g_a2d[D_COLS];          // ||A_j||^2 (double)
__device__ double g_S2d[S_COLS];          // ||S_c||^2 (double)
__device__ int    g_match[D_COLS];
__device__ int    g_sel[S_COLS];
__device__ int    g_Cidx[NC];
__device__ int    g_U[NUP];
__device__ double g_Afro2d;
__device__ int    g_offset;
__device__ float  g_Asub[N_ROWS * NUP];   // A[:, U]   (8192 x 96)
__device__ float  g_Cpart[KPARTS * D_COLS * NUP];  // k-split partials of C
__device__ float  g_Csub[D_COLS * NUP];   // K[:, U]   (1024 x 96), deterministic
__device__ float  g_K2part[4 * NU * NU];
__device__ int    g_needfix[NPAIR];
__device__ double g_obj[NPAIR];
__device__ int    g_out[S_COLS];

// inline views (bit-identical to the old materialized Ksub/K2sub)
__device__ __forceinline__ float kval(int i, int j) {
    return g_Csub[g_U[i] * NUP + j];
}
__device__ __forceinline__ float k2val(int i, int j) {
    int t = i * NU + j;
    return ((g_K2part[t] + g_K2part[NU * NU + t]) +
            g_K2part[2 * NU * NU + t]) + g_K2part[3 * NU * NU + t];
}

// ---------------- packed f32x2 helpers (Blackwell) ----------------
__device__ __forceinline__ unsigned long long pk2(float x, float y) {
    unsigned long long r;
    asm("mov.b64 %0, {%1, %2};" : "=l"(r) : "f"(x), "f"(y));
    return r;
}
__device__ __forceinline__ void upk2(unsigned long long v, float& x, float& y) {
    asm("mov.b64 {%0, %1}, %2;" : "=f"(x), "=f"(y) : "l"(v));
}
__device__ __forceinline__ void fma2(unsigned long long& d,
                                     unsigned long long a, unsigned long long b) {
    asm("fma.rn.f32x2 %0, %1, %2, %3;" : "=l"(d) : "l"(a), "l"(b), "l"(d));
}

// ---------------- cp.async helpers ----------------
__device__ __forceinline__ unsigned smem_u32(const void* p) {
    return (unsigned)__cvta_generic_to_shared(p);
}
#define CP_ASYNC16(dst_u32, src_ptr) \
    asm volatile("cp.async.cg.shared.global [%0], [%1], 16;" \
                 :: "r"(dst_u32), "l"(src_ptr))
#define CP_COMMIT() asm volatile("cp.async.commit_group;" ::: "memory")
#define CP_WAIT1()  asm volatile("cp.async.wait_group 1;" ::: "memory")
#define CP_WAIT0()  asm volatile("cp.async.wait_group 0;" ::: "memory")

// ---------------- JAX threefry2x32 (exact) ----------------
__device__ __forceinline__ unsigned tf_rotl(unsigned v, int r) {
    return (v << r) | (v >> (32 - r));
}
__device__ void threefry2x32(unsigned k0, unsigned k1, unsigned x0, unsigned x1,
                             unsigned& o0, unsigned& o1) {
    unsigned ks2 = k0 ^ k1 ^ 0x1BD11BDAu;
    x0 += k0; x1 += k1;
    const int R0[4] = {13, 15, 26, 6};
    const int R1[4] = {17, 29, 16, 24};
#pragma unroll
    for (int i = 0; i < 4; i++) { x0 += x1; x1 = tf_rotl(x1, R0[i]); x1 ^= x0; }
    x0 += k1; x1 += ks2 + 1u;
#pragma unroll
    for (int i = 0; i < 4; i++) { x0 += x1; x1 = tf_rotl(x1, R1[i]); x1 ^= x0; }
    x0 += ks2; x1 += k0 + 2u;
#pragma unroll
    for (int i = 0; i < 4; i++) { x0 += x1; x1 = tf_rotl(x1, R0[i]); x1 ^= x0; }
    x0 += k0; x1 += k1 + 3u;
#pragma unroll
    for (int i = 0; i < 4; i++) { x0 += x1; x1 = tf_rotl(x1, R1[i]); x1 ^= x0; }
    x0 += k1; x1 += ks2 + 4u;
#pragma unroll
    for (int i = 0; i < 4; i++) { x0 += x1; x1 = tf_rotl(x1, R0[i]); x1 ^= x0; }
    x0 += ks2; x1 += k0 + 5u;
    o0 = x0; o1 = x1;
}
__device__ __forceinline__ unsigned tf_bits(unsigned k0, unsigned k1,
                                            unsigned x0, unsigned x1) {
    unsigned o0, o1; threefry2x32(k0, k1, x0, x1, o0, o1);
    return o0 ^ o1;
}

// ---------------- symmetric Jacobi eigensolver (double, n<=9) ----------------
__device__ void jacobi_sym(double* A, double* V, int n) {
    for (int i = 0; i < n * n; i++) V[i] = 0.0;
    for (int i = 0; i < n; i++) V[i * n + i] = 1.0;
    for (int sweep = 0; sweep < 20; sweep++) {
        double off = 0.0, dsc = 1e-300;
        for (int p = 0; p < n; p++) {
            dsc += A[p * n + p] * A[p * n + p];
            for (int q = p + 1; q < n; q++) off += A[p * n + q] * A[p * n + q];
        }
        if (off <= dsc * 1e-28) break;
        for (int p = 0; p < n - 1; p++)
            for (int q = p + 1; q < n; q++) {
                double apq = A[p * n + q];
                if (fabs(apq) < 1e-300) continue;
                double app = A[p * n + p], aqq = A[q * n + q];
                double theta = 0.5 * (aqq - app) / apq;
                double t = ((theta >= 0.0) ? 1.0 : -1.0) /
                           (fabs(theta) + sqrt(1.0 + theta * theta));
                double c = 1.0 / sqrt(1.0 + t * t), s = t * c;
                for (int k2 = 0; k2 < n; k2++) {
                    if (k2 == p || k2 == q) continue;
                    double akp = A[k2 * n + p], akq = A[k2 * n + q];
                    A[k2 * n + p] = A[p * n + k2] = c * akp - s * akq;
                    A[k2 * n + q] = A[q * n + k2] = s * akp + c * akq;
                }
                A[p * n + p] = app - t * apq;
                A[q * n + q] = aqq + t * apq;
                A[p * n + q] = A[q * n + p] = 0.0;
                for (int k2 = 0; k2 < n; k2++) {
                    double vkp = V[k2 * n + p], vkq = V[k2 * n + q];
                    V[k2 * n + p] = c * vkp - s * vkq;
                    V[k2 * n + q] = s * vkp + c * vkq;
                }
            }
    }
}

// ---------------- kernels ----------------

// per-column ||A_j||^2 (Kahan fp32 -> double) and B = S^T A (f32x2 packed)
// strided-column layout (round-14 proven)
__global__ void stats_kernel(const float* __restrict__ A, const float* __restrict__ S) {
    int tid = threadIdx.x;                 // 256
    int r0 = blockIdx.x * 32;              // 256 blocks
    float a2s[4], a2c[4];
    unsigned long long bacc2[4][4];
    double s2acc = 0.0;
#pragma unroll
    for (int a = 0; a < 4; a++) {
        a2s[a] = 0.0f; a2c[a] = 0.0f;
#pragma unroll
        for (int b = 0; b < 4; b++) bacc2[a][b] = 0ULL;
    }
    for (int rr = 0; rr < 32; rr++) {
        int row = r0 + rr;
        float sv[8];
#pragma unroll
        for (int c = 0; c < 8; c++) sv[c] = __ldg(&S[row * 8 + c]);
        unsigned long long svp[4];
#pragma unroll
        for (int c = 0; c < 4; c++) svp[c] = pk2(sv[2 * c], sv[2 * c + 1]);
        if (tid < 8) s2acc += (double)sv[tid] * (double)sv[tid];
        const float* Ar = A + (size_t)row * D_COLS;
#pragma unroll
        for (int c4 = 0; c4 < 4; c4++) {
            float v = Ar[tid + c4 * 256];
            float y = fmaf(v, v, -a2c[c4]);
            float t = a2s[c4] + y;
            a2c[c4] = (t - a2s[c4]) - y;
            a2s[c4] = t;
            unsigned long long vv = pk2(v, v);
#pragma unroll
            for (int c = 0; c < 4; c++) fma2(bacc2[c4][c], vv, svp[c]);
        }
    }
#pragma unroll
    for (int c4 = 0; c4 < 4; c4++) {
        int col = tid + c4 * 256;
        atomicAdd(&g_a2d[col], (double)a2s[c4] + (double)a2c[c4]);
#pragma unroll
        for (int c = 0; c < 4; c++) {
            float lo, hi;
            upk2(bacc2[c4][c], lo, hi);
            atomicAdd(&g_B[(2 * c) * D_COLS + col], lo);
            atomicAdd(&g_B[(2 * c + 1) * D_COLS + col], hi);
        }
    }
    if (tid < 8) atomicAdd(&g_S2d[tid], s2acc);
}

// merged: G_S, inv(G_S), col_norms, match, logits, sel, offset, bitonic top-80
__global__ void __launch_bounds__(1024) setup_topk_kernel(const float* __restrict__ S) {
    __shared__ float sTri[36];
    __shared__ float sGS[64];
    __shared__ double sred[1024];
    __shared__ double sW[64];
    __shared__ float sWf[64];
    __shared__ double sSn[8];
    __shared__ double sL[64];
    __shared__ int sFallback;
    __shared__ float sv_[D_COLS];
    __shared__ int six_[D_COLS];
    int tid = threadIdx.x;       // 1024
    int lane = tid & 31;
    if (tid < 36) sTri[tid] = 0.0f;
    if (tid == 0) sFallback = 0;
    __syncthreads();

    // G_S = S^T S
    {
        float g[36];
#pragma unroll
        for (int i = 0; i < 36; i++) g[i] = 0.0f;
        for (int r = tid; r < N_ROWS; r += 1024) {
            float sv[8];
#pragma unroll
            for (int c = 0; c < 8; c++) sv[c] = S[r * 8 + c];
            int w = 0;
#pragma unroll
            for (int c = 0; c < 8; c++)
#pragma unroll
                for (int d = c; d < 8; d++) { g[w] += sv[c] * sv[d]; w++; }
        }
#pragma unroll
        for (int i = 0; i < 36; i++) {
            float x = g[i];
#pragma unroll
            for (int off = 16; off; off >>= 1)
                x += __shfl_down_sync(0xffffffffu, x, off);
            if (lane == 0) atomicAdd(&sTri[i], x);
        }
    }
    __syncthreads();
    if (tid < 64) {
        int c = tid >> 3, d = tid & 7;
        int lo = c < d ? c : d, hi = c < d ? d : c;
        int w = lo * 8 - lo * (lo - 1) / 2 + (hi - lo);
        sGS[tid] = sTri[w];
    }
    if (tid >= 64 && tid < 72) sSn[tid - 64] = sqrt(g_S2d[tid - 64]);

    // A_fro2
    {
        double p = (tid < D_COLS) ? g_a2d[tid] : 0.0;
        sred[tid] = p; __syncthreads();
        for (int st = 512; st > 0; st >>= 1) {
            if (tid < st) sred[tid] += sred[tid + st];
            __syncthreads();
        }
        if (tid == 0) g_Afro2d = sred[0];
        __syncthreads();
    }

    // inv(G_S) via Cholesky; fallback Jacobi pinv
    if (tid == 0) {
        double L[64];
        int ok = 1;
        for (int c = 0; c < 8 && ok; c++) {
            double d = (double)sGS[c * 8 + c];
            for (int k = 0; k < c; k++) d -= L[c * 8 + k] * L[c * 8 + k];
            if (d <= 0.0) { ok = 0; break; }
            double lc = sqrt(d);
            L[c * 8 + c] = lc;
            for (int r = c + 1; r < 8; r++) {
                double v = (double)sGS[r * 8 + c];
                for (int k = 0; k < c; k++) v -= L[r * 8 + k] * L[c * 8 + k];
                L[r * 8 + c] = v / lc;
            }
        }
        if (ok) {
            for (int i = 0; i < 64; i++) sL[i] = L[i];
        } else {
            sFallback = 1;
            double Ad[64], Vd[64];
            for (int i = 0; i < 64; i++) Ad[i] = (double)sGS[i];
            jacobi_sym(Ad, Vd, 8);
            double lmax = 0.0;
            for (int r = 0; r < 8; r++) lmax = fmax(lmax, fabs(Ad[r * 8 + r]));
            double cut = 9.5367431640625e-06 * lmax;
            for (int c = 0; c < 8; c++)
                for (int d = 0; d < 8; d++) {
                    double w = 0.0;
                    for (int r = 0; r < 8; r++) {
                        double lam = Ad[r * 8 + r];
                        if (fabs(lam) > cut) w += Vd[c * 8 + r] * Vd[d * 8 + r] / lam;
                    }
                    sW[c * 8 + d] = w;
                }
        }
    }
    __syncthreads();
    if (!sFallback && tid < 8) {
        double y[8], x[8];
        for (int r = 0; r < 8; r++) {
            double v = (r == tid) ? 1.0 : 0.0;
            for (int k = 0; k < r; k++) v -= sL[r * 8 + k] * y[k];
            y[r] = v / sL[r * 8 + r];
        }
        for (int r = 7; r >= 0; r--) {
            double v = y[r];
            for (int k = r + 1; k < 8; k++) v -= sL[k * 8 + r] * x[k];
            x[r] = v / sL[r * 8 + r];
        }
        for (int r = 0; r < 8; r++) sW[r * 8 + tid] = x[r];
    }
    __syncthreads();
    if (tid < 64) sWf[tid] = (float)sW[tid];
    __syncthreads();

    // col_norms in fp32 (feeds only Gumbel logits); match on double norms
    float cn;
    {
        int j = tid;
        float b[8];
#pragma unroll
        for (int c = 0; c < 8; c++) b[c] = g_B[c * D_COLS + j];
        float q = 0.0f;
#pragma unroll
        for (int c = 0; c < 8; c++) {
            float w = 0.0f;
#pragma unroll
            for (int d = 0; d < 8; d++) w += sWf[c * 8 + d] * b[d];
            q += b[c] * w;
        }
        double a2 = g_a2d[j];
        cn = fmaxf((float)a2 - q, 0.0f);
        double an = sqrt(a2);
        double th = 1e-5 * (an + 1e-10);
        int mt = 0;
#pragma unroll
        for (int c = 0; c < 8; c++)
            if (fabs(sSn[c] - an) < th) mt = 1;
        g_match[j] = mt;
    }
    __syncthreads();

    // denominator (double tree; common shift -> ordering-invariant)
    sred[tid] = (double)cn;
    __syncthreads();
    for (int st = 512; st > 0; st >>= 1) {
        if (tid < st) sred[tid] += sred[tid + st];
        __syncthreads();
    }
    float denom = (float)sred[0];
    __syncthreads();

    // logits
    {
        unsigned kg0, kg1;
        threefry2x32(0u, 42u, 0u, 0u, kg0, kg1);
        unsigned bits = tf_bits(kg0, kg1, 0u, (unsigned)tid);
        float u = __uint_as_float((bits >> 9) | 0x3f800000u) - 1.0f;
        u = fmaxf(u, 0.0f);
        float gum = -logf(-logf(u + EPSF) + EPSF);
        sv_[tid] = logf(cn / (denom + EPSF) + EPSF) + gum;
        six_[tid] = tid;
    }

    if (tid == 0) {
        unsigned km0, km1;
        threefry2x32(0u, 42u, 0u, 1u, km0, km1);
        unsigned k1a, k1b, k2a, k2b;
        threefry2x32(km0, km1, 0u, 0u, k1a, k1b);
        threefry2x32(km0, km1, 0u, 1u, k2a, k2b);
        unsigned hb = tf_bits(k1a, k1b, 0u, 0u);
        unsigned lb = tf_bits(k2a, k2b, 0u, 0u);
        g_offset = (int)((((hb % 80u) * 16u) + (lb % 80u)) % 80u);
    }
    __syncthreads();
    if (tid == 0) {
        int cnt = 0;
        int selL[8];
        for (int j = 0; j < D_COLS && cnt < 8; j++)
            if (g_match[j]) selL[cnt++] = j;
        for (int j = 0; j < D_COLS && cnt < 8; j++)
            if (!g_match[j]) selL[cnt++] = j;
        for (int x = 1; x < 8; x++) {
            int v = selL[x], y = x - 1;
            while (y >= 0 && selL[y] > v) { selL[y + 1] = selL[y]; y--; }
            selL[y + 1] = v;
        }
        for (int c = 0; c < 8; c++) { g_sel[c] = selL[c]; g_U[c] = selL[c]; }
    }
    __syncthreads();

    // bitonic sort (value desc, ties -> lower index)
    for (int k = 2; k <= D_COLS; k <<= 1) {
        for (int j = k >> 1; j > 0; j >>= 1) {
            int l = tid ^ j;
            if (l > tid) {
                float vi = sv_[tid], vl = sv_[l];
                int ii = six_[tid], il = six_[l];
                bool lt = (vl > vi) || (vl == vi && il < ii);
                bool dirAsc = ((tid & k) == 0);
                if (lt == dirAsc) {
                    sv_[tid] = vl; sv_[l] = vi;
                    six_[tid] = il; six_[l] = ii;
                }
            }
            __syncthreads();
        }
    }
    if (tid < NC) { g_Cidx[tid] = six_[tid]; g_U[8 + tid] = six_[tid]; }
    if (tid >= NU && tid < NUP) g_U[tid] = g_sel[0];   // padding
}

__global__ void gather_kernel(const float* __restrict__ A) {
    int t = blockIdx.x * blockDim.x + threadIdx.x;
    if (t >= N_ROWS * NUP) return;
    int i = t / NUP, u = t - i * NUP;
    g_Asub[t] = A[(size_t)i * D_COLS + g_U[u]];
}

// C = A^T * Asub (1024 x 96): round-14 proven config — cp.async double-buffer,
// 256 threads, 4j x 12u tiling, 2 blocks/SM, deterministic k-partial STG.
__global__ void __launch_bounds__(256, 2) matmul_C_kernel(const float* __restrict__ A) {
    __shared__ __align__(16) float sA[2][16][128];
    __shared__ __align__(16) float sB[2][16][NUP];
    int j0 = blockIdx.x * 128;       // 8 j-tiles
    int part = blockIdx.y;           // 32 k-parts
    int i0 = part * 256;
    int tid = threadIdx.x;           // 256
    int tj = (tid & 31) * 4;         // 4 consecutive j
    int tu = (tid >> 5) * 12;        // 12 consecutive u
    unsigned long long acc2[4][6];
#pragma unroll
    for (int a = 0; a < 4; a++)
#pragma unroll
        for (int p = 0; p < 6; p++) acc2[a][p] = 0ULL;

    int aR0 = tid >> 5;                     // 0..7
    int aR1 = (tid + 256) >> 5;             // 8..15
    int aC  = (tid & 31) * 4;
    int bR0 = tid / 24,         bC0 = (tid % 24) * 4;
    int bR1 = (tid + 256) / 24, bC1 = ((tid + 256) % 24) * 4;
    bool hasB1 = tid < 128;

#define MM_ISSUE(ch, buf) do {                                               \
        int ib_ = i0 + (ch) * 16;                                            \
        CP_ASYNC16(smem_u32(&sA[buf][aR0][aC]),                              \
                   &A[(size_t)(ib_ + aR0) * D_COLS + j0 + aC]);              \
        CP_ASYNC16(smem_u32(&sA[buf][aR1][aC]),                              \
                   &A[(size_t)(ib_ + aR1) * D_COLS + j0 + aC]);              \
        CP_ASYNC16(smem_u32(&sB[buf][bR0][bC0]),                             \
                   &g_Asub[(ib_ + bR0) * NUP + bC0]);                        \
        if (hasB1)                                                           \
            CP_ASYNC16(smem_u32(&sB[buf][bR1][bC1]),                         \
                       &g_Asub[(ib_ + bR1) * NUP + bC1]);                    \
        CP_COMMIT();                                                         \
    } while (0)

    MM_ISSUE(0, 0);
    for (int ch = 0; ch < 16; ch++) {
        int buf = ch & 1;
        if (ch < 15) { MM_ISSUE(ch + 1, buf ^ 1); CP_WAIT1(); }
        else         { CP_WAIT0(); }
        __syncthreads();
#pragma unroll
        for (int kk = 0; kk < 16; kk++) {
            float4 aj = *(float4*)&sA[buf][kk][tj];
            unsigned long long avp[4];
            avp[0] = pk2(aj.x, aj.x);
            avp[1] = pk2(aj.y, aj.y);
            avp[2] = pk2(aj.z, aj.z);
            avp[3] = pk2(aj.w, aj.w);
            ulonglong2 q0 = *(const ulonglong2*)&sB[buf][kk][tu];
            ulonglong2 q1 = *(const ulonglong2*)&sB[buf][kk][tu + 4];
            ulonglong2 q2 = *(const ulonglong2*)&sB[buf][kk][tu + 8];
            unsigned long long bv[6] = {q0.x, q0.y, q1.x, q1.y, q2.x, q2.y};
#pragma unroll
            for (int p = 0; p < 6; p++)
#pragma unroll
                for (int a = 0; a < 4; a++) fma2(acc2[a][p], avp[a], bv[p]);
        }
        __syncthreads();
    }
#undef MM_ISSUE
    float* dst = &g_Cpart[(size_t)part * (D_COLS * NUP)];
#pragma unroll
    for (int a = 0; a < 4; a++) {
        int base = (j0 + tj + a) * NUP + tu;
#pragma unroll
        for (int p = 0; p < 6; p++) {
            float lo, hi;
            upk2(acc2[a][p], lo, hi);
            __stwt((float2*)&dst[base + 2 * p], make_float2(lo, hi));
        }
    }
}

// deterministic sum of k-partials -> Csub (fixed ascending part order)
__global__ void csub_sum_kernel() {
    int t = blockIdx.x * blockDim.x + threadIdx.x;
    if (t >= D_COLS * NUP) return;
    float s = 0.0f;
#pragma unroll 4
    for (int p = 0; p < KPARTS; p++)
        s += g_Cpart[(size_t)p * (D_COLS * NUP) + t];
    g_Csub[t] = s;
}

// K2 partials = C^T C over m-quarter (deterministic, no atomics)
__global__ void ksub_part_kernel() {
    __shared__ float sI[32][17];
    __shared__ float sJ[32][17];
    int i0 = blockIdx.y * 16, j0 = blockIdx.x * 16;
    int mz = blockIdx.z;                      // 0..3
    int tx = threadIdx.x, ty = threadIdx.y;   // 16 x 16
    float acc = 0.0f;
    for (int m0 = mz * 256; m0 < mz * 256 + 256; m0 += 32) {
        int r = ty * 2 + (tx >> 3);
        int c = tx & 7;
        sI[r][c * 2]     = g_Csub[(m0 + r) * NUP + i0 + c * 2];
        sI[r][c * 2 + 1] = g_Csub[(m0 + r) * NUP + i0 + c * 2 + 1];
        sJ[r][c * 2]     = g_Csub[(m0 + r) * NUP + j0 + c * 2];
        sJ[r][c * 2 + 1] = g_Csub[(m0 + r) * NUP + j0 + c * 2 + 1];
        __syncthreads();
#pragma unroll
        for (int mm = 0; mm < 32; mm++)
            acc += sI[mm][ty] * sJ[mm][tx];
        __syncthreads();
    }
    int i = i0 + ty, j = j0 + tx;
    if (i < NU && j < NU)
        g_K2part[mz * NU * NU + i * NU + j] = acc;
}

// fully-unrolled Cholesky + trace(G^-1 M); operands via inline kval/k2val
template <int N>
__device__ bool chol_trace(const int* idx, double& out) {
    double L[N * N];
#pragma unroll
    for (int c = 0; c < N; c++) {
        double d = (double)kval(idx[c], idx[c]);
#pragma unroll
        for (int k = 0; k < N; k++)
            if (k < c) d -= L[c * N + k] * L[c * N + k];
        if (d <= 0.0) return false;
        double lc = sqrt(d);
        L[c * N + c] = lc;
#pragma unroll
        for (int r = 0; r < N; r++)
            if (r > c) {
                double v = (double)kval(idx[r], idx[c]);
#pragma unroll
                for (int k = 0; k < N; k++)
                    if (k < c) v -= L[r * N + k] * L[c * N + k];
                L[r * N + c] = v / lc;
            }
    }
    double sum = 0.0;
#pragma unroll
    for (int c = 0; c < N; c++) {
        double y[N], x[N];
#pragma unroll
        for (int r = 0; r < N; r++) {
            double v = (double)k2val(idx[r], idx[c]);
#pragma unroll
            for (int k = 0; k < N; k++)
                if (k < r) v -= L[r * N + k] * y[k];
            y[r] = v / L[r * N + r];
        }
#pragma unroll
        for (int r = N - 1; r >= 0; r--) {
            double v = y[r];
#pragma unroll
            for (int k = 0; k < N; k++)
                if (k > r) v -= L[k * N + r] * x[k];
            x[r] = v / L[r * N + r];
        }
        sum += x[c];
    }
    out = sum;
    return true;
}

// fast path only; flags hard cases for finalize's fixup
__global__ void pairs_fast_kernel() {
    int pid = blockIdx.x * blockDim.x + threadIdx.x;
    if (pid >= NPAIR) return;
    int a = pid >> 3, qpos = pid & 7;
    int pg = g_Cidx[a];
    bool pMasked = (pg == g_sel[qpos]);
    bool dup = false;
#pragma unroll
    for (int r = 0; r < 8; r++)
        if (r != qpos && g_sel[r] == pg) dup = true;
    if (dup) { g_needfix[pid] = 1; return; }
    int idx[9]; int n = 0;
#pragma unroll
    for (int r = 0; r < 8; r++)
        if (r != qpos) idx[n++] = r;
    if (!pMasked) idx[n++] = 8 + a;
    double sum;
    bool ok = pMasked ? chol_trace<7>(idx, sum) : chol_trace<8>(idx, sum);
    if (!ok) { g_needfix[pid] = 1; return; }
    g_obj[pid] = sqrt(fmax(g_Afro2d - sum, 0.0));
}

// fixup (rare) + argmin + output-index construction
__global__ void finalize_kernel() {
    int tid = threadIdx.x;   // 256
    for (int pid = tid; pid < NPAIR; pid += 256) {
        if (!g_needfix[pid]) continue;
        int a = pid >> 3, qpos = pid & 7;
        int pg = g_Cidx[a];
        double m[9];
#pragma unroll
        for (int r = 0; r < 9; r++) m[r] = 1.0;
        m[qpos] = 0.0;
        if (pg == g_sel[qpos]) m[8] = 0.0;
        int pos[9];
#pragma unroll
        for (int r = 0; r < 8; r++) pos[r] = r;
        pos[8] = 8 + a;
        double G[81], M[81], V[81];
        for (int r = 0; r < 9; r++)
            for (int c = 0; c < 9; c++) {
                double mm = m[r] * m[c];
                G[r * 9 + c] = mm * (double)kval(pos[r], pos[c]);
                M[r * 9 + c] = mm * (double)k2val(pos[r], pos[c]);
            }
        jacobi_sym(G, V, 9);
        double lmax = 0.0;
        for (int r = 0; r < 9; r++) lmax = fmax(lmax, fabs(G[r * 9 + r]));
        double cutoff = 1.0728836059570312e-05 * lmax;  // 10*9*eps_f32
        double sum = 0.0;
        for (int r = 0; r < 9; r++) {
            double lam = G[r * 9 + r];
            if (fabs(lam) > cutoff) {
                double quad = 0.0;
                for (int i = 0; i < 9; i++) {
                    double wi = 0.0;
                    for (int j = 0; j < 9; j++) wi += M[i * 9 + j] * V[j * 9 + r];
                    quad += V[i * 9 + r] * wi;
                }
                sum += quad / lam;
            }
        }
        g_obj[pid] = sqrt(fmax(g_Afro2d - sum, 0.0));
    }
    __syncthreads();
    if (tid >= 32) return;
    int lane = tid;
    double bv = 1e300; int bi = NPAIR;
    for (int p = lane; p < NPAIR; p += 32) {
        double v = g_obj[p];
        if (v < bv) { bv = v; bi = p; }
    }
#pragma unroll
    for (int off = 16; off; off >>= 1) {
        double ov = __shfl_down_sync(0xffffffffu, bv, off);
        int oi = __shfl_down_sync(0xffffffffu, bi, off);
        if (ov < bv || (ov == bv && oi < bi)) { bv = ov; bi = oi; }
    }
    if (lane != 0) return;
    int qpos = bi & 7;
    int minidx = g_sel[qpos];
    int bestp = g_Cidx[g_offset];
    int out[8]; int cnt = 0;
    for (int j = 0; j < D_COLS && cnt < 8; j++) {
        int f = g_match[j];
        if (j == minidx) f = 0;
        if (j == bestp) f = 1;
        if (f) out[cnt++] = j;
    }
    for (int j = 0; j < D_COLS && cnt < 8; j++) {
        int f = g_match[j];
        if (j == minidx) f = 0;
        if (j == bestp) f = 1;
        if (!f) out[cnt++] = j;
    }
    for (int x = 1; x < 8; x++) {
        int v = out[x], y = x - 1;
        while (y >= 0 && out[y] > v) { out[y + 1] = out[y]; y--; }
        out[y + 1] = v;
    }
    for (int c = 0; c < 8; c++) g_out[c] = out[c];
}

// output gather + re-zero scratch for the next graph replay
__global__ void output_kernel(const float* __restrict__ A, float* __restrict__ out) {
    int t = blockIdx.x * blockDim.x + threadIdx.x;   // 65536 threads
    if (t < N_ROWS * S_COLS) {
        int i = t >> 3, c = t & 7;
        out[t] = A[(size_t)i * D_COLS + g_out[c]];
    }
    if (t < S_COLS * D_COLS) g_B[t] = 0.0f;
    if (t < D_COLS) g_a2d[t] = 0.0;
    if (t < S_COLS) g_S2d[t] = 0.0;
    if (t < NPAIR) g_needfix[t] = 0;
}

// ---------------- launch ----------------
extern "C" void kernel_launch(void* const* d_in, const int* in_sizes, int n_in,
                              void* d_out, int out_size) {
    const float* A = nullptr;
    const float* S = nullptr;
    for (int i = 0; i < n_in; i++) {
        if (in_sizes[i] == N_ROWS * D_COLS) A = (const float*)d_in[i];
        else if (in_sizes[i] == N_ROWS * S_COLS) S = (const float*)d_in[i];
    }
    if (!A) A = (const float*)d_in[0];
    if (!S) S = (const float*)d_in[2];
    float* out = (float*)d_out;

    stats_kernel<<<256, 256>>>(A, S);
    setup_topk_kernel<<<1, 1024>>>(S);
    gather_kernel<<<(N_ROWS * NUP) / 256, 256>>>(A);
    matmul_C_kernel<<<dim3(8, KPARTS), 256>>>(A);
    csub_sum_kernel<<<(D_COLS * NUP + 255) / 256, 256>>>();
    ksub_part_kernel<<<dim3(6, 6, 4), dim3(16, 16)>>>();
    pairs_fast_kernel<<<(NPAIR + 63) / 64, 64>>>();
    finalize_kernel<<<1, 256>>>();
    output_kernel<<<(N_ROWS * S_COLS) / 256, 256>>>(A, out);
}